// round 5
// baseline (speedup 1.0000x reference)
#include <cuda_runtime.h>
#include <cuda_fp16.h>
#include <math.h>

// RegionalAttentionPool: B=16, N=4096, D=512, R=64, K=128
// Pass 1: stream x once -> scores y[b,n] = x.W + bias, AND write fp16 copy
//         of x (64 MB, fits L2) to device scratch.
// Pass 2: per-(b,r) softmax over gathered scores + weighted sum gathering
//         fp16 rows (L2-resident), fp32 accumulation.

constexpr int Bc = 16;
constexpr int Nc = 4096;
constexpr int Dc = 512;
constexpr int Rc = 64;
constexpr int Kc = 128;
constexpr int D4 = Dc / 4;       // 128 float4 per row

__device__ float g_scores[Bc * Nc];                     // 256 KB
__device__ __half g_xh[(size_t)Bc * Nc * Dc];           // 64 MiB fp16 copy of x

// ---------------------------------------------------------------------------
// Pass 1: one warp per row, 16 rows/CTA. Reads x once, writes fp16 copy.
// ---------------------------------------------------------------------------
__global__ __launch_bounds__(512, 2)
void score_convert_pass(const float4* __restrict__ x4,
                        const float4* __restrict__ W4,
                        const float*  __restrict__ bias,
                        float*        __restrict__ y)
{
    const int lane = threadIdx.x & 31;
    const int warp = threadIdx.x >> 5;                 // 0..15
    const int row  = blockIdx.x * 16 + warp;           // 0 .. B*N-1

    const float4* __restrict__ xr = x4 + (size_t)row * D4;
    uint2* __restrict__ xh = (uint2*)(g_xh + (size_t)row * Dc);  // 4 halfs per uint2

    float dot = 0.0f;
    #pragma unroll
    for (int j = 0; j < 4; j++) {
        float4 v = xr[j * 32 + lane];
        float4 w = W4[j * 32 + lane];
        dot = fmaf(v.x, w.x, dot);
        dot = fmaf(v.y, w.y, dot);
        dot = fmaf(v.z, w.z, dot);
        dot = fmaf(v.w, w.w, dot);

        __half2 h0 = __floats2half2_rn(v.x, v.y);
        __half2 h1 = __floats2half2_rn(v.z, v.w);
        uint2 packed;
        packed.x = *(unsigned int*)&h0;
        packed.y = *(unsigned int*)&h1;
        xh[j * 32 + lane] = packed;
    }
    #pragma unroll
    for (int off = 16; off > 0; off >>= 1)
        dot += __shfl_xor_sync(0xffffffffu, dot, off);

    if (lane == 0) y[row] = dot + bias[0];
}

// ---------------------------------------------------------------------------
// Pass 2: one CTA per (b,r), 128 threads. Thread = 4 consecutive d (one uint2
// of halfs per row). Softmax in prologue; hot loop is pure LDG.64 + HFMA->FFMA.
// ---------------------------------------------------------------------------
__global__ __launch_bounds__(128)
void pool_pass(const int*   __restrict__ ridx,
               const float* __restrict__ y,
               float4*      __restrict__ out4)
{
    __shared__ float s_w[Kc];
    __shared__ int   s_off[Kc];     // row offsets in units of uint2-chunks
    __shared__ float s_red[4];

    const int tid  = threadIdx.x;      // 0..127
    const int lane = tid & 31;
    const int warp = tid >> 5;         // 0..3
    const int r    = blockIdx.x % Rc;
    const int b    = blockIdx.x / Rc;

    // --- softmax over the 128 gathered scores (thread = one k) ---
    const int idx = ridx[r * Kc + tid];
    s_off[tid] = (b * Nc + idx) * (Dc / 4);   // chunk offset of row start
    float s = y[b * Nc + idx];

    float m = s;
    #pragma unroll
    for (int off = 16; off > 0; off >>= 1)
        m = fmaxf(m, __shfl_xor_sync(0xffffffffu, m, off));
    if (lane == 0) s_red[warp] = m;
    __syncthreads();
    m = fmaxf(fmaxf(s_red[0], s_red[1]), fmaxf(s_red[2], s_red[3]));

    float e = __expf(s - m);

    float l = e;
    #pragma unroll
    for (int off = 16; off > 0; off >>= 1)
        l += __shfl_xor_sync(0xffffffffu, l, off);
    __syncthreads();
    if (lane == 0) s_red[warp] = l;
    __syncthreads();
    l = (s_red[0] + s_red[1]) + (s_red[2] + s_red[3]);

    s_w[tid] = e / l;
    __syncthreads();

    // --- weighted sum: 128 fp16 rows, uint2 (4 halfs) per thread, MLP=8 ---
    const uint2* __restrict__ xh = (const uint2*)g_xh;

    float ax = 0.f, ay = 0.f, az = 0.f, aw = 0.f;

    #pragma unroll 1
    for (int g = 0; g < Kc; g += 8) {
        uint2 v[8];
        #pragma unroll
        for (int j = 0; j < 8; j++)
            v[j] = xh[(size_t)s_off[g + j] + tid];
        #pragma unroll
        for (int j = 0; j < 8; j++) {
            const float wk = s_w[g + j];
            float2 f0 = __half22float2(*(__half2*)&v[j].x);
            float2 f1 = __half22float2(*(__half2*)&v[j].y);
            ax = fmaf(wk, f0.x, ax);
            ay = fmaf(wk, f0.y, ay);
            az = fmaf(wk, f1.x, az);
            aw = fmaf(wk, f1.y, aw);
        }
    }

    out4[(size_t)blockIdx.x * Kc + tid] = make_float4(ax, ay, az, aw);
}

extern "C" void kernel_launch(void* const* d_in, const int* in_sizes, int n_in,
                              void* d_out, int out_size)
{
    const float4* x4   = (const float4*)d_in[0];   // (B, N, D) f32
    const int*    ridx = (const int*)   d_in[1];   // (R, K) i32
    const float4* W4   = (const float4*)d_in[2];   // (1, D) f32
    const float*  bias = (const float*) d_in[3];   // (1,) f32

    float* y = nullptr;
    cudaGetSymbolAddress((void**)&y, g_scores);

    score_convert_pass<<<(Bc * Nc) / 16, 512>>>(x4, W4, bias, y);
    pool_pass<<<Bc * Rc, 128>>>(ridx, y, (float4*)d_out);
    (void)in_sizes; (void)n_in; (void)out_size;
}

// round 6
// speedup vs baseline: 1.1732x; 1.1732x over previous
#include <cuda_runtime.h>
#include <math.h>

// RegionalAttentionPool: B=16, N=4096, D=512, R=64, K=128
// Pass 1: dense scores y[b,n] = x[b,n,:].W + bias (reads x once, BW-bound).
// Pass 2: one CTA per (b, r, d-slice): softmax over 128 gathered scores
//         (redundant per slice, cheap) + weighted float2 gather-accumulate.
//         4 slices per (b,r) -> 4096 CTAs for occupancy / MLP.

constexpr int Bc = 16;
constexpr int Nc = 4096;
constexpr int Dc = 512;
constexpr int Rc = 64;
constexpr int Kc = 128;
constexpr int D4 = Dc / 4;        // 128 float4 per row
constexpr int D2 = Dc / 2;        // 256 float2 per row
constexpr int SLICES = 4;         // D split into 4 slices of 128 floats
constexpr int SLICE_F2 = D2 / SLICES;  // 64... no: 256/4 = 64 float2 per slice? -> use 128 threads x float2 => slice = 128 float2 = 256 floats; SLICES=2? see below

// Recompute: 128 threads * float2 = 256 floats per slice -> 2 slices cover D=512.
// For 4 slices use 64 threads? Better: 4 slices x 128 floats, thread = 1 float.
// Chosen layout: SLICES=4, 128 threads, each thread loads ONE float per row.
// 128 threads * 4B = 512B contiguous per row-slice (4 sectors) — still coalesced.

__device__ float g_scores[Bc * Nc];   // 256 KB scratch

// ---------------------------------------------------------------------------
// Pass 1: one warp per row. 512 threads = 16 rows/CTA. Reads x once (dense).
// ---------------------------------------------------------------------------
__global__ __launch_bounds__(512, 2)
void score_pass(const float4* __restrict__ x4,
                const float4* __restrict__ W4,
                const float*  __restrict__ bias,
                float*        __restrict__ y)
{
    const int lane = threadIdx.x & 31;
    const int warp = threadIdx.x >> 5;                 // 0..15
    const int row  = blockIdx.x * 16 + warp;           // 0 .. B*N-1

    const float4* __restrict__ xr = x4 + (size_t)row * D4;

    float dot = 0.0f;
    #pragma unroll
    for (int j = 0; j < 4; j++) {
        float4 v = xr[j * 32 + lane];
        float4 w = W4[j * 32 + lane];
        dot = fmaf(v.x, w.x, dot);
        dot = fmaf(v.y, w.y, dot);
        dot = fmaf(v.z, w.z, dot);
        dot = fmaf(v.w, w.w, dot);
    }
    #pragma unroll
    for (int off = 16; off > 0; off >>= 1)
        dot += __shfl_xor_sync(0xffffffffu, dot, off);

    if (lane == 0) y[row] = dot + bias[0];
}

// ---------------------------------------------------------------------------
// Pass 2: grid = (SLICES=2, B*R). 128 threads, thread = one float2 of its
// 256-float slice. Softmax in prologue; hot loop pure LDG.64 + FFMA, MLP=8.
// ---------------------------------------------------------------------------
__global__ __launch_bounds__(128)
void pool_pass(const float2* __restrict__ x2,
               const int*    __restrict__ ridx,
               const float*  __restrict__ y,
               float2*       __restrict__ out2)
{
    __shared__ float s_w[Kc];
    __shared__ int   s_off[Kc];     // row-slice start offsets (float2 units)
    __shared__ float s_red[4];

    const int tid   = threadIdx.x;     // 0..127
    const int lane  = tid & 31;
    const int warp  = tid >> 5;        // 0..3
    const int slice = blockIdx.x;      // 0..1
    const int br    = blockIdx.y;      // 0..1023
    const int r     = br % Rc;
    const int b     = br / Rc;

    // --- softmax over the 128 gathered scores (thread = one k) ---
    const int idx = ridx[r * Kc + tid];
    s_off[tid] = (b * Nc + idx) * D2 + slice * 128;
    float s = y[b * Nc + idx];

    float m = s;
    #pragma unroll
    for (int off = 16; off > 0; off >>= 1)
        m = fmaxf(m, __shfl_xor_sync(0xffffffffu, m, off));
    if (lane == 0) s_red[warp] = m;
    __syncthreads();
    m = fmaxf(fmaxf(s_red[0], s_red[1]), fmaxf(s_red[2], s_red[3]));

    float e = __expf(s - m);

    float l = e;
    #pragma unroll
    for (int off = 16; off > 0; off >>= 1)
        l += __shfl_xor_sync(0xffffffffu, l, off);
    __syncthreads();
    if (lane == 0) s_red[warp] = l;
    __syncthreads();
    l = (s_red[0] + s_red[1]) + (s_red[2] + s_red[3]);

    s_w[tid] = e / l;
    __syncthreads();

    // --- weighted sum: 128 rows, one float2 per thread per row, MLP=8 ---
    float ax = 0.f, ay = 0.f;

    #pragma unroll 1
    for (int g = 0; g < Kc; g += 8) {
        float2 v[8];
        #pragma unroll
        for (int j = 0; j < 8; j++)
            v[j] = x2[(size_t)s_off[g + j] + tid];
        #pragma unroll
        for (int j = 0; j < 8; j++) {
            const float wk = s_w[g + j];
            ax = fmaf(wk, v[j].x, ax);
            ay = fmaf(wk, v[j].y, ay);
        }
    }

    out2[(size_t)br * D2 + slice * 128 + tid] = make_float2(ax, ay);
}

extern "C" void kernel_launch(void* const* d_in, const int* in_sizes, int n_in,
                              void* d_out, int out_size)
{
    const float4* x4   = (const float4*)d_in[0];   // (B, N, D) f32
    const float2* x2   = (const float2*)d_in[0];
    const int*    ridx = (const int*)   d_in[1];   // (R, K) i32
    const float4* W4   = (const float4*)d_in[2];   // (1, D) f32
    const float*  bias = (const float*) d_in[3];   // (1,) f32

    float* y = nullptr;
    cudaGetSymbolAddress((void**)&y, g_scores);

    score_pass<<<(Bc * Nc) / 16, 512>>>(x4, W4, bias, y);

    dim3 grid(2, Bc * Rc);    // 2 slices of 256 floats each, 2048 CTAs
    pool_pass<<<grid, 128>>>(x2, ridx, y, (float2*)d_out);
    (void)in_sizes; (void)n_in; (void)out_size;
}